// round 1
// baseline (speedup 1.0000x reference)
#include <cuda_runtime.h>
#include <math.h>

#define NS 1024
#define HD 256
#define XD 128

// scratch (device globals: no allocation allowed)
__device__ float g_xp[NS * HD];   // x @ Wx
__device__ float g_yp[NS * HD];   // y @ Wy + b1
__device__ double g_es;           // sum over all (i,j) of exp(dot_ij)
__device__ double g_ds;           // sum over i of dot_ii

typedef unsigned long long u64;

__device__ __forceinline__ u64 pk2(float a, float b) {
    u64 r; asm("mov.b64 %0, {%1, %2};" : "=l"(r) : "f"(a), "f"(b)); return r;
}
__device__ __forceinline__ void up2(u64 v, float& a, float& b) {
    asm("mov.b64 {%0, %1}, %2;" : "=f"(a), "=f"(b) : "l"(v));
}
__device__ __forceinline__ u64 add2(u64 a, u64 b) {
    u64 r; asm("add.rn.f32x2 %0, %1, %2;" : "=l"(r) : "l"(a), "l"(b)); return r;
}
__device__ __forceinline__ u64 fma2(u64 a, u64 b, u64 c) {
    u64 r; asm("fma.rn.f32x2 %0, %1, %2, %3;" : "=l"(r) : "l"(a), "l"(b), "l"(c)); return r;
}

__global__ void k_init() { g_es = 0.0; g_ds = 0.0; }

// xp = x @ W1[:128]; yp = y @ W1[128:] + b1
// 128 blocks: blocks 0..63 handle x rows, 64..127 handle y rows. 16 rows/block.
__global__ void __launch_bounds__(256) k_gemm(
    const float* __restrict__ x, const float* __restrict__ y,
    const float* __restrict__ W1, const float* __restrict__ b1)
{
    __shared__ __align__(16) float xs[128 * 18];  // [k][r], padded stride 18
    int b = blockIdx.x;
    int isY = b >> 6;
    int row0 = (b & 63) << 4;
    const float* src = isY ? y : x;
    const float* W = W1 + isY * (XD * HD);
    int t = threadIdx.x;

    #pragma unroll
    for (int p = 0; p < 8; p++) {
        int idx = t + p * 256;
        int r = idx >> 7, k = idx & 127;
        xs[k * 18 + r] = src[(row0 + r) * XD + k];
    }
    __syncthreads();

    int c = t;  // output column 0..255
    u64 acc[8];
    #pragma unroll
    for (int m = 0; m < 8; m++) acc[m] = 0ull;

    #pragma unroll 8
    for (int k = 0; k < 128; k++) {
        float w = W[k * HD + c];
        u64 wd = pk2(w, w);
        #pragma unroll
        for (int m = 0; m < 8; m++) {
            u64 xv = *(const u64*)&xs[k * 18 + 2 * m];  // rows (2m, 2m+1)
            acc[m] = fma2(xv, wd, acc[m]);
        }
    }

    float bias = isY ? b1[c] : 0.0f;
    float* dst = isY ? g_yp : g_xp;
    #pragma unroll
    for (int m = 0; m < 8; m++) {
        float v0, v1; up2(acc[m], v0, v1);
        dst[(row0 + 2 * m)     * HD + c] = v0 + bias;
        dst[(row0 + 2 * m + 1) * HD + c] = v1 + bias;
    }
}

// Pairwise kernel: CTA = 64x64 tile of (i,j); 256 threads; thread = 4i x 4j pairs.
// k packed in f32x2 (2 k's per op). Smem XOR-swizzled for conflict-free reads.
__global__ void __launch_bounds__(256, 2) k_pair(const float* __restrict__ W2)
{
    __shared__ __align__(16) float2 xsh[64 * 32];  // j rows, KC=64 (32 f2)
    __shared__ __align__(16) float2 ysh[64 * 32];  // i rows
    __shared__ __align__(16) float2 wsh[128];      // all 256 W2 values
    __shared__ float red[16];

    int t = threadIdx.x;
    int tx = t & 15, ty = t >> 4;
    int jT = blockIdx.x << 6, iT = blockIdx.y << 6;

    if (t < 128) wsh[t] = ((const float2*)W2)[t];

    const float2* gx = (const float2*)g_xp;  // [1024][128]
    const float2* gy = (const float2*)g_yp;

    u64 acc[16];
    #pragma unroll
    for (int p = 0; p < 16; p++) acc[p] = 0ull;

    int lr = t >> 5;   // loader base row 0..7
    int lc = t & 31;   // loader f2 column

    #pragma unroll 1
    for (int ch = 0; ch < 4; ch++) {
        int kc2 = ch * 32;
        __syncthreads();  // protect previous chunk reads (and wsh on first pass)
        #pragma unroll
        for (int m = 0; m < 8; m++) {
            int row = lr + 8 * m;
            int slot = row * 32 + (lc ^ (row & 15));
            xsh[slot] = gx[(jT + row) * 128 + kc2 + lc];
            ysh[slot] = gy[(iT + row) * 128 + kc2 + lc];
        }
        __syncthreads();

        #pragma unroll 8
        for (int k2 = 0; k2 < 32; k2++) {
            u64 w = *(const u64*)&wsh[kc2 + k2];
            int ox = k2 ^ tx, oy = k2 ^ ty;
            u64 xv[4], yv[4];
            #pragma unroll
            for (int a = 0; a < 4; a++)
                xv[a] = *(const u64*)&xsh[(tx + 16 * a) * 32 + ox];
            #pragma unroll
            for (int bq = 0; bq < 4; bq++)
                yv[bq] = *(const u64*)&ysh[(ty + 16 * bq) * 32 + oy];
            #pragma unroll
            for (int bq = 0; bq < 4; bq++) {
                #pragma unroll
                for (int a = 0; a < 4; a++) {
                    u64 tt = add2(xv[a], yv[bq]);
                    float lo, hi; up2(tt, lo, hi);
                    lo = fmaxf(lo, 0.0f);
                    hi = fmaxf(hi, 0.0f);
                    acc[bq * 4 + a] = fma2(pk2(lo, hi), w, acc[bq * 4 + a]);
                }
            }
        }
    }

    // epilogue: per-pair dot -> exp-sum + diagonal capture
    float le = 0.0f, ld = 0.0f;
    #pragma unroll
    for (int bq = 0; bq < 4; bq++) {
        #pragma unroll
        for (int a = 0; a < 4; a++) {
            float lo, hi; up2(acc[bq * 4 + a], lo, hi);
            float s = lo + hi;
            le += __expf(s);
            int gi = iT + ty + 16 * bq;
            int gj = jT + tx + 16 * a;
            if (gi == gj) ld += s;
        }
    }

    #pragma unroll
    for (int o = 16; o > 0; o >>= 1) {
        le += __shfl_xor_sync(0xffffffffu, le, o);
        ld += __shfl_xor_sync(0xffffffffu, ld, o);
    }
    int wid = t >> 5, lane = t & 31;
    __syncthreads();
    if (lane == 0) { red[wid] = le; red[8 + wid] = ld; }
    __syncthreads();
    if (t == 0) {
        float se = 0.0f, sd = 0.0f;
        #pragma unroll
        for (int w2i = 0; w2i < 8; w2i++) { se += red[w2i]; sd += red[8 + w2i]; }
        atomicAdd(&g_es, (double)se);
        if (iT == jT) atomicAdd(&g_ds, (double)sd);
    }
}

// LB = (diag_mean + b2) - e^{b2-1} * grand_exp_sum / n^2
__global__ void k_final(float* out, const float* __restrict__ b2)
{
    double b = (double)b2[0];
    double lb = g_ds / (double)NS + b
              - exp(b - 1.0) * g_es / ((double)NS * (double)NS);
    out[0] = (float)lb;
}

extern "C" void kernel_launch(void* const* d_in, const int* in_sizes, int n_in,
                              void* d_out, int out_size)
{
    (void)in_sizes; (void)n_in; (void)out_size;
    const float* x  = (const float*)d_in[0];
    const float* y  = (const float*)d_in[1];
    const float* W1 = (const float*)d_in[2];
    const float* b1 = (const float*)d_in[3];
    const float* W2 = (const float*)d_in[4];
    const float* b2 = (const float*)d_in[5];

    k_init<<<1, 1>>>();
    k_gemm<<<128, 256>>>(x, y, W1, b1);
    k_pair<<<dim3(16, 16), 256>>>(W2);
    k_final<<<1, 1>>>((float*)d_out, b2);
}

// round 2
// speedup vs baseline: 1.1009x; 1.1009x over previous
#include <cuda_runtime.h>
#include <math.h>

#define NS 1024
#define HD 256
#define XD 128
#define S2 34   // smem row stride in float2 units (68 words == 4 mod 32 -> LDS.128 conflict-free)

// scratch (device globals: no allocation allowed)
__device__ float g_xp[NS * HD];   // x @ Wx
__device__ float g_yp[NS * HD];   // y @ Wy + b1
__device__ double g_es;           // sum over all (i,j) of exp(dot_ij)
__device__ double g_ds;           // sum over i of dot_ii
__device__ unsigned int g_cnt;    // k_pair completion counter

typedef unsigned long long u64;

__device__ __forceinline__ u64 pk2(float a, float b) {
    u64 r; asm("mov.b64 %0, {%1, %2};" : "=l"(r) : "f"(a), "f"(b)); return r;
}
__device__ __forceinline__ void up2(u64 v, float& a, float& b) {
    asm("mov.b64 {%0, %1}, %2;" : "=f"(a), "=f"(b) : "l"(v));
}
__device__ __forceinline__ u64 add2(u64 a, u64 b) {
    u64 r; asm("add.rn.f32x2 %0, %1, %2;" : "=l"(r) : "l"(a), "l"(b)); return r;
}
__device__ __forceinline__ u64 fma2(u64 a, u64 b, u64 c) {
    u64 r; asm("fma.rn.f32x2 %0, %1, %2, %3;" : "=l"(r) : "l"(a), "l"(b), "l"(c)); return r;
}

// xp = x @ W1[:128]; yp = y @ W1[128:] + b1. Also zeroes the global reducers.
// 128 blocks: blocks 0..63 -> x rows, 64..127 -> y rows. 16 rows/block.
__global__ void __launch_bounds__(256) k_gemm(
    const float* __restrict__ x, const float* __restrict__ y,
    const float* __restrict__ W1, const float* __restrict__ b1)
{
    if (blockIdx.x == 0 && threadIdx.x == 0) {
        g_es = 0.0; g_ds = 0.0; g_cnt = 0u;
    }

    __shared__ __align__(16) float xs[128 * 18];  // [k][r], padded stride 18
    int b = blockIdx.x;
    int isY = b >> 6;
    int row0 = (b & 63) << 4;
    const float* src = isY ? y : x;
    const float* W = W1 + isY * (XD * HD);
    int t = threadIdx.x;

    #pragma unroll
    for (int p = 0; p < 8; p++) {
        int idx = t + p * 256;
        int r = idx >> 7, k = idx & 127;
        xs[k * 18 + r] = src[(row0 + r) * XD + k];
    }
    __syncthreads();

    int c = t;  // output column 0..255
    u64 acc[8];
    #pragma unroll
    for (int m = 0; m < 8; m++) acc[m] = 0ull;

    #pragma unroll 8
    for (int k = 0; k < 128; k++) {
        float w = W[k * HD + c];
        u64 wd = pk2(w, w);
        #pragma unroll
        for (int m = 0; m < 8; m++) {
            u64 xv = *(const u64*)&xs[k * 18 + 2 * m];  // rows (2m, 2m+1)
            acc[m] = fma2(xv, wd, acc[m]);
        }
    }

    float bias = isY ? b1[c] : 0.0f;
    float* dst = isY ? g_yp : g_xp;
    #pragma unroll
    for (int m = 0; m < 8; m++) {
        float v0, v1; up2(acc[m], v0, v1);
        dst[(row0 + 2 * m)     * HD + c] = v0 + bias;
        dst[(row0 + 2 * m + 1) * HD + c] = v1 + bias;
    }
}

// Pairwise kernel: CTA = 64x64 tile of (i,j); 256 threads; thread = 4i x 4j pairs.
// Padded smem layout (stride S2=34 f2) -> all inner-loop LDS are .128 with
// immediate offsets, conflict-free. Last block computes the final scalar.
__global__ void __launch_bounds__(256, 2) k_pair(
    const float* __restrict__ W2, const float* __restrict__ b2,
    float* __restrict__ out)
{
    __shared__ __align__(16) float2 xsh[64 * S2];  // j rows, 32 f2 data + 2 pad
    __shared__ __align__(16) float2 ysh[64 * S2];  // i rows
    __shared__ __align__(16) float2 wsh[128];      // all 256 W2 values
    __shared__ float red[16];

    int t = threadIdx.x;
    int tx = t & 15, ty = t >> 4;
    int jT = blockIdx.x << 6, iT = blockIdx.y << 6;

    if (t < 128) wsh[t] = ((const float2*)W2)[t];

    const float4* gx = (const float4*)g_xp;  // 64 f4 per row of 256 floats
    const float4* gy = (const float4*)g_yp;

    u64 acc[16];
    #pragma unroll
    for (int p = 0; p < 16; p++) acc[p] = 0ull;

    float4* xs4 = (float4*)xsh;   // 17 f4 per row
    float4* ys4 = (float4*)ysh;

    #pragma unroll 1
    for (int ch = 0; ch < 4; ch++) {
        __syncthreads();  // protect previous chunk reads (and wsh on first pass)
        // fill: 64 rows x 16 f4 per array = 1024 f4; 4 per thread per array
        #pragma unroll
        for (int p = 0; p < 4; p++) {
            int idx = t + p * 256;
            int row = idx >> 4, c4 = idx & 15;
            xs4[row * 17 + c4] = gx[(jT + row) * 64 + ch * 16 + c4];
            ys4[row * 17 + c4] = gy[(iT + row) * 64 + ch * 16 + c4];
        }
        __syncthreads();

        #pragma unroll 8
        for (int j2 = 0; j2 < 16; j2++) {       // each j2 covers 4 k values
            ulonglong2 wv = *(const ulonglong2*)&wsh[ch * 32 + 2 * j2];
            ulonglong2 xq[4], yq[4];
            #pragma unroll
            for (int a = 0; a < 4; a++)
                xq[a] = *(const ulonglong2*)&xsh[(tx + 16 * a) * S2 + 2 * j2];
            #pragma unroll
            for (int bq = 0; bq < 4; bq++)
                yq[bq] = *(const ulonglong2*)&ysh[(ty + 16 * bq) * S2 + 2 * j2];
            #pragma unroll
            for (int bq = 0; bq < 4; bq++) {
                #pragma unroll
                for (int a = 0; a < 4; a++) {
                    u64 t0 = add2(xq[a].x, yq[bq].x);
                    float l0, h0; up2(t0, l0, h0);
                    l0 = fmaxf(l0, 0.0f); h0 = fmaxf(h0, 0.0f);
                    acc[bq * 4 + a] = fma2(pk2(l0, h0), wv.x, acc[bq * 4 + a]);
                    u64 t1 = add2(xq[a].y, yq[bq].y);
                    float l1, h1; up2(t1, l1, h1);
                    l1 = fmaxf(l1, 0.0f); h1 = fmaxf(h1, 0.0f);
                    acc[bq * 4 + a] = fma2(pk2(l1, h1), wv.y, acc[bq * 4 + a]);
                }
            }
        }
    }

    // epilogue: per-pair dot -> exp-sum + diagonal capture
    float le = 0.0f, ld = 0.0f;
    #pragma unroll
    for (int bq = 0; bq < 4; bq++) {
        #pragma unroll
        for (int a = 0; a < 4; a++) {
            float lo, hi; up2(acc[bq * 4 + a], lo, hi);
            float s = lo + hi;
            le += __expf(s);
            int gi = iT + ty + 16 * bq;
            int gj = jT + tx + 16 * a;
            if (gi == gj) ld += s;
        }
    }

    #pragma unroll
    for (int o = 16; o > 0; o >>= 1) {
        le += __shfl_xor_sync(0xffffffffu, le, o);
        ld += __shfl_xor_sync(0xffffffffu, ld, o);
    }
    int wid = t >> 5, lane = t & 31;
    __syncthreads();
    if (lane == 0) { red[wid] = le; red[8 + wid] = ld; }
    __syncthreads();
    if (t == 0) {
        float se = 0.0f, sd = 0.0f;
        #pragma unroll
        for (int w2i = 0; w2i < 8; w2i++) { se += red[w2i]; sd += red[8 + w2i]; }
        atomicAdd(&g_es, (double)se);
        if (iT == jT) atomicAdd(&g_ds, (double)sd);
        __threadfence();
        unsigned int c = atomicAdd(&g_cnt, 1u);
        if (c == 255u) {
            // last block: all partials are visible (fenced adds ordered by g_cnt)
            double es = atomicAdd(&g_es, 0.0);   // read full sums
            double ds = atomicAdd(&g_ds, 0.0);
            double bb = (double)b2[0];
            double lb = ds / (double)NS + bb
                      - exp(bb - 1.0) * es / ((double)NS * (double)NS);
            out[0] = (float)lb;
        }
    }
}

extern "C" void kernel_launch(void* const* d_in, const int* in_sizes, int n_in,
                              void* d_out, int out_size)
{
    (void)in_sizes; (void)n_in; (void)out_size;
    const float* x  = (const float*)d_in[0];
    const float* y  = (const float*)d_in[1];
    const float* W1 = (const float*)d_in[2];
    const float* b1 = (const float*)d_in[3];
    const float* W2 = (const float*)d_in[4];
    const float* b2 = (const float*)d_in[5];

    k_gemm<<<128, 256>>>(x, y, W1, b1);
    k_pair<<<dim3(16, 16), 256>>>(W2, b2, (float*)d_out);
}